// round 4
// baseline (speedup 1.0000x reference)
#include <cuda_runtime.h>

#define N_NODES 100000
#define N_EDGES 1600000
#define HID 64
#define DENSE 128
#define OUTD 10
#define N_GRAPHS 128
#define SCAN_NB 98   // ceil(100000/1024)
#define INVN (1.f / (float)N_NODES)

typedef unsigned long long u64t;

// ---------------- packed f32x2 helpers ------------------------------------
__device__ __forceinline__ u64t pk2(float lo, float hi) {
    u64t r;
    asm("mov.b64 %0,{%1,%2};" : "=l"(r) : "f"(lo), "f"(hi));
    return r;
}
__device__ __forceinline__ void fma2(u64t& d, u64t a, u64t b) {
    asm("fma.rn.f32x2 %0,%1,%2,%0;" : "+l"(d) : "l"(a), "l"(b));
}
__device__ __forceinline__ float2 up2(u64t v) {
    float2 r;
    asm("mov.b64 {%0,%1},%2;" : "=f"(r.x), "=f"(r.y) : "l"(v));
    return r;
}

// ---------------- device scratch ------------------------------------------
__device__ __align__(16) float g_Xa[N_NODES * HID];
__device__ __align__(16) float g_Xb[N_NODES * HID];
__device__ __align__(16) float g_Y1[N_NODES * DENSE];
__device__ int   g_deg[N_NODES];
__device__ int   g_rowptr[N_NODES];
__device__ int   g_cursor[N_NODES];
__device__ int   g_col[N_EDGES];
__device__ int   g_bsum[128];
__device__ __align__(16) float g_stats128[4 * 2 * DENSE];  // per-layer
__device__ __align__(16) float g_stats64 [4 * 2 * HID];    // per-layer
__device__ __align__(16) float g_statsF[2 * DENSE];
__device__ __align__(16) float g_tfF[2 * DENSE];
__device__ __align__(16) float g_reps[N_GRAPHS * HID];
__device__ __align__(16) float g_T1[N_GRAPHS * DENSE];
__device__ __align__(16) float g_T2[N_GRAPHS * DENSE];

// ---------------- setup ---------------------------------------------------
__global__ void k_setup() {
    int t = blockIdx.x * blockDim.x + threadIdx.x;
    if (t < N_NODES)          g_deg[t] = 0;
    if (t < 4 * 2 * DENSE)    g_stats128[t] = 0.f;
    if (t < 4 * 2 * HID)      g_stats64[t]  = 0.f;
    if (t < 2 * DENSE)        g_statsF[t] = 0.f;
}

// ---------------- CSR build (keyed by dst, values = src) ------------------
__global__ void k_hist(const int* __restrict__ ei) {
    int e = blockIdx.x * blockDim.x + threadIdx.x;
    if (e < N_EDGES) atomicAdd(&g_deg[ei[N_EDGES + e]], 1);
}

__global__ void k_scan1() {
    __shared__ int ss[256];
    int tid = threadIdx.x;
    int base = blockIdx.x * 1024 + tid * 4;
    int s = 0;
#pragma unroll
    for (int i = 0; i < 4; i++) {
        int idx = base + i;
        if (idx < N_NODES) s += g_deg[idx];
    }
    ss[tid] = s; __syncthreads();
    for (int off = 128; off > 0; off >>= 1) {
        if (tid < off) ss[tid] += ss[tid + off];
        __syncthreads();
    }
    if (tid == 0) g_bsum[blockIdx.x] = ss[0];
}

__global__ void k_scan2(int nblk) {
    __shared__ int ws[4];
    int t = threadIdx.x, lane = t & 31, w = t >> 5;
    int orig = (t < nblk) ? g_bsum[t] : 0;
    int v = orig;
#pragma unroll
    for (int o = 1; o < 32; o <<= 1) {
        int n = __shfl_up_sync(0xFFFFFFFFu, v, o);
        if (lane >= o) v += n;
    }
    if (lane == 31) ws[w] = v;
    __syncthreads();
    int add = 0;
    for (int i = 0; i < w; i++) add += ws[i];
    v += add;
    if (t < nblk) g_bsum[t] = v - orig;
}

__global__ void k_scan3() {
    __shared__ int sc[256];
    int tid = threadIdx.x;
    int base = blockIdx.x * 1024 + tid * 4;
    int d[4]; int s = 0;
#pragma unroll
    for (int i = 0; i < 4; i++) {
        d[i] = (base + i < N_NODES) ? g_deg[base + i] : 0;
        s += d[i];
    }
    sc[tid] = s; __syncthreads();
    for (int off = 1; off < 256; off <<= 1) {
        int v = (tid >= off) ? sc[tid - off] : 0;
        __syncthreads();
        sc[tid] += v;
        __syncthreads();
    }
    int off = g_bsum[blockIdx.x] + sc[tid] - s;
#pragma unroll
    for (int i = 0; i < 4; i++) {
        if (base + i < N_NODES) { g_rowptr[base + i] = off; g_cursor[base + i] = off; off += d[i]; }
    }
}

__global__ void k_fill(const int* __restrict__ ei) {
    int e = blockIdx.x * blockDim.x + threadIdx.x;
    if (e < N_EDGES) {
        int d = ei[N_EDGES + e];
        int p = atomicAdd(&g_cursor[d], 1);
        g_col[p] = ei[e];
    }
}

// ============ GEMM1 fused with GIN aggregation ============================
// Block: 128 rows x 128 cols, 512 threads, 1 CTA/SM.
// A tile built in-kernel: sA[row] = (1+eps)*f(x[row]) + sum_nbr f(x[nbr]),
// f = relu(BN affine) for l>=1, f = emb lookup for l==0.
// Mainloop: k-paired FFMA2, W transposed in smem.
#define SA1 68                       // 64 + 4 pad
#define G1_SMEM_FLOATS (128*SA1 + 128*SA1 + 2*HID + 2*DENSE)
__global__ void __launch_bounds__(512, 1) k_gemm1f(
        const int* __restrict__ x_idx, const float* __restrict__ emb,
        const float* __restrict__ X, const float* __restrict__ epsArr,
        const float* __restrict__ W, float* __restrict__ Y,
        const float* __restrict__ statsIn, const float* __restrict__ gam,
        const float* __restrict__ bet, float* __restrict__ statsOut, int layer) {
    extern __shared__ float sm[];
    float* sA  = sm;                     // [128][SA1]
    float* sWT = sm + 128 * SA1;         // [128 cols][SA1]
    float* sa  = sWT + 128 * SA1;        // [64]
    float* sb  = sa + HID;               // [64]
    float* sS  = sb + HID;               // [256]
    int t = threadIdx.x;
    int row0 = blockIdx.x * 128;

    if (t < HID && layer > 0) {
        float s = statsIn[t], q = statsIn[HID + t];
        float m = s * INVN;
        float var = q * INVN - m * m;
        float a = gam[t] * rsqrtf(var + 1e-5f);
        sa[t] = a;
        sb[t] = fmaf(-m, a, bet[t]);
    }
    if (t < 256) sS[t] = 0.f;
    // W transpose: W[k][c] -> sWT[c][k]
    for (int idx = t; idx < HID * DENSE; idx += 512) {
        int k = idx >> 7, c = idx & 127;
        sWT[c * SA1 + k] = W[idx];
    }
    __syncthreads();

    // ---- gather: 4 threads per row, 16 cols each ----
    {
        int row = t >> 2, th = t & 3, c0 = th * 16;
        int gr = row0 + row;
        float acc[16];
#pragma unroll
        for (int i = 0; i < 16; i++) acc[i] = 0.f;
        if (gr < N_NODES) {
            int start = g_rowptr[gr], deg = g_deg[gr];
            float ev = 1.f + epsArr[layer];
            if (layer == 0) {
                int si = __ldg(&x_idx[gr]);
                const float4* er = (const float4*)(emb + (size_t)si * HID + c0);
#pragma unroll
                for (int i = 0; i < 4; i++) {
                    float4 v = er[i];
                    acc[4 * i + 0] = ev * v.x; acc[4 * i + 1] = ev * v.y;
                    acc[4 * i + 2] = ev * v.z; acc[4 * i + 3] = ev * v.w;
                }
                int j = 0;
                for (; j + 1 < deg; j += 2) {
                    int n0 = __ldg(&x_idx[g_col[start + j]]);
                    int n1 = __ldg(&x_idx[g_col[start + j + 1]]);
                    const float4* r0 = (const float4*)(emb + (size_t)n0 * HID + c0);
                    const float4* r1 = (const float4*)(emb + (size_t)n1 * HID + c0);
#pragma unroll
                    for (int i = 0; i < 4; i++) {
                        float4 p = r0[i], q = r1[i];
                        acc[4 * i + 0] += p.x + q.x; acc[4 * i + 1] += p.y + q.y;
                        acc[4 * i + 2] += p.z + q.z; acc[4 * i + 3] += p.w + q.w;
                    }
                }
                if (j < deg) {
                    int n0 = __ldg(&x_idx[g_col[start + j]]);
                    const float4* r0 = (const float4*)(emb + (size_t)n0 * HID + c0);
#pragma unroll
                    for (int i = 0; i < 4; i++) {
                        float4 p = r0[i];
                        acc[4 * i + 0] += p.x; acc[4 * i + 1] += p.y;
                        acc[4 * i + 2] += p.z; acc[4 * i + 3] += p.w;
                    }
                }
            } else {
                float4 ta[4], tb[4];
#pragma unroll
                for (int i = 0; i < 4; i++) {
                    ta[i] = *(const float4*)(sa + c0 + 4 * i);
                    tb[i] = *(const float4*)(sb + c0 + 4 * i);
                }
                {   // self
                    const float4* xr = (const float4*)(X + (size_t)gr * HID + c0);
#pragma unroll
                    for (int i = 0; i < 4; i++) {
                        float4 p = xr[i];
                        acc[4 * i + 0] = ev * fmaxf(fmaf(ta[i].x, p.x, tb[i].x), 0.f);
                        acc[4 * i + 1] = ev * fmaxf(fmaf(ta[i].y, p.y, tb[i].y), 0.f);
                        acc[4 * i + 2] = ev * fmaxf(fmaf(ta[i].z, p.z, tb[i].z), 0.f);
                        acc[4 * i + 3] = ev * fmaxf(fmaf(ta[i].w, p.w, tb[i].w), 0.f);
                    }
                }
                int j = 0;
                for (; j + 1 < deg; j += 2) {
                    int n0 = g_col[start + j], n1 = g_col[start + j + 1];
                    const float4* r0 = (const float4*)(X + (size_t)n0 * HID + c0);
                    const float4* r1 = (const float4*)(X + (size_t)n1 * HID + c0);
#pragma unroll
                    for (int i = 0; i < 4; i++) {
                        float4 p = r0[i], q = r1[i];
                        acc[4 * i + 0] += fmaxf(fmaf(ta[i].x, p.x, tb[i].x), 0.f)
                                        + fmaxf(fmaf(ta[i].x, q.x, tb[i].x), 0.f);
                        acc[4 * i + 1] += fmaxf(fmaf(ta[i].y, p.y, tb[i].y), 0.f)
                                        + fmaxf(fmaf(ta[i].y, q.y, tb[i].y), 0.f);
                        acc[4 * i + 2] += fmaxf(fmaf(ta[i].z, p.z, tb[i].z), 0.f)
                                        + fmaxf(fmaf(ta[i].z, q.z, tb[i].z), 0.f);
                        acc[4 * i + 3] += fmaxf(fmaf(ta[i].w, p.w, tb[i].w), 0.f)
                                        + fmaxf(fmaf(ta[i].w, q.w, tb[i].w), 0.f);
                    }
                }
                if (j < deg) {
                    int n0 = g_col[start + j];
                    const float4* r0 = (const float4*)(X + (size_t)n0 * HID + c0);
#pragma unroll
                    for (int i = 0; i < 4; i++) {
                        float4 p = r0[i];
                        acc[4 * i + 0] += fmaxf(fmaf(ta[i].x, p.x, tb[i].x), 0.f);
                        acc[4 * i + 1] += fmaxf(fmaf(ta[i].y, p.y, tb[i].y), 0.f);
                        acc[4 * i + 2] += fmaxf(fmaf(ta[i].z, p.z, tb[i].z), 0.f);
                        acc[4 * i + 3] += fmaxf(fmaf(ta[i].w, p.w, tb[i].w), 0.f);
                    }
                }
            }
        }
#pragma unroll
        for (int i = 0; i < 4; i++)
            *(float4*)(sA + row * SA1 + c0 + 4 * i) =
                make_float4(acc[4 * i], acc[4 * i + 1], acc[4 * i + 2], acc[4 * i + 3]);
    }
    __syncthreads();

    // ---- mainloop: 8 rows x 4 cols per thread, k-paired FFMA2 ----
    int tx = t & 31, ty = t >> 5;
    const float* aB = sA + ty * 8 * SA1;
    u64t acc[8][4];
#pragma unroll
    for (int i = 0; i < 8; i++)
#pragma unroll
        for (int j = 0; j < 4; j++) acc[i][j] = pk2(0.f, 0.f);

#pragma unroll 4
    for (int k4 = 0; k4 < HID; k4 += 4) {
        u64t w01[4], w23[4];
#pragma unroll
        for (int jj = 0; jj < 4; jj++) {
            float4 wv = *(const float4*)(sWT + (tx + 32 * jj) * SA1 + k4);
            w01[jj] = pk2(wv.x, wv.y); w23[jj] = pk2(wv.z, wv.w);
        }
#pragma unroll
        for (int i = 0; i < 8; i++) {
            float4 av = *(const float4*)(aB + i * SA1 + k4);
            u64t a01 = pk2(av.x, av.y), a23 = pk2(av.z, av.w);
#pragma unroll
            for (int jj = 0; jj < 4; jj++) {
                fma2(acc[i][jj], a01, w01[jj]);
                fma2(acc[i][jj], a23, w23[jj]);
            }
        }
    }

    float cs[4] = {0.f, 0.f, 0.f, 0.f}, cq[4] = {0.f, 0.f, 0.f, 0.f};
#pragma unroll
    for (int i = 0; i < 8; i++) {
        int gr = row0 + ty * 8 + i;
#pragma unroll
        for (int jj = 0; jj < 4; jj++) {
            float2 p = up2(acc[i][jj]);
            float v = p.x + p.y;
            if (gr < N_NODES) Y[(size_t)gr * DENSE + tx + 32 * jj] = v;
            cs[jj] += v; cq[jj] += v * v;
        }
    }
#pragma unroll
    for (int jj = 0; jj < 4; jj++) {
        atomicAdd(&sS[tx + 32 * jj], cs[jj]);
        atomicAdd(&sS[DENSE + tx + 32 * jj], cq[jj]);
    }
    __syncthreads();
    if (t < 256) atomicAdd(&statsOut[t], sS[t]);
}

// ============ GEMM2: X' = relu(BN(Y1)) @ W2 (k-paired FFMA2) ==============
#define SA2 132                      // 128 + 4 pad
#define G2_SMEM_FLOATS (128*SA2 + 64*SA2 + 3*DENSE)
__global__ void __launch_bounds__(256, 2) k_gemm2(const float* __restrict__ Yin,
                                                  const float* __restrict__ W,
                                                  float* __restrict__ Xout,
                                                  const float* __restrict__ statsIn,
                                                  const float* __restrict__ gam,
                                                  const float* __restrict__ bet,
                                                  float* __restrict__ statsOut) {
    extern __shared__ float sm[];
    float* sA  = sm;                   // [128][SA2]
    float* sWT = sm + 128 * SA2;       // [64 cols][SA2]
    float* sTa = sWT + 64 * SA2;       // [128]
    float* sTb = sTa + DENSE;          // [128]
    float* sS  = sTb + DENSE;          // [128]
    int t = threadIdx.x;
    int row0 = blockIdx.x * 128;

    if (t < DENSE) {
        float s = statsIn[t], q = statsIn[DENSE + t];
        float m = s * INVN;
        float var = q * INVN - m * m;
        float a = gam[t] * rsqrtf(var + 1e-5f);
        sTa[t] = a;
        sTb[t] = fmaf(-m, a, bet[t]);
    }
    if (t < 128) sS[t] = 0.f;
    __syncthreads();

    // W transpose: W[k][c] (128x64) -> sWT[c][k]
    for (int idx = t; idx < DENSE * HID; idx += 256) {
        int k = idx >> 6, c = idx & 63;
        sWT[c * SA2 + k] = W[idx];
    }
    {   // A tile with BN+relu transform
        int r = t >> 1, kh = (t & 1) * 64;
        int gr = row0 + r;
        float4* dst = (float4*)(sA + r * SA2 + kh);
        if (gr < N_NODES) {
            const float4* src = (const float4*)(Yin + (size_t)gr * DENSE + kh);
#pragma unroll
            for (int i = 0; i < 16; i++) {
                float4 y = src[i];
                float4 ta = *(const float4*)(sTa + kh + i * 4);
                float4 tb = *(const float4*)(sTb + kh + i * 4);
                float4 v;
                v.x = fmaxf(fmaf(ta.x, y.x, tb.x), 0.f);
                v.y = fmaxf(fmaf(ta.y, y.y, tb.y), 0.f);
                v.z = fmaxf(fmaf(ta.z, y.z, tb.z), 0.f);
                v.w = fmaxf(fmaf(ta.w, y.w, tb.w), 0.f);
                dst[i] = v;
            }
        } else {
#pragma unroll
            for (int i = 0; i < 16; i++) dst[i] = make_float4(0.f, 0.f, 0.f, 0.f);
        }
    }
    __syncthreads();

    int tx = t & 15, ty = t >> 4;
    const float* aB = sA + ty * 8 * SA2;
    u64t acc[8][4];
#pragma unroll
    for (int i = 0; i < 8; i++)
#pragma unroll
        for (int j = 0; j < 4; j++) acc[i][j] = pk2(0.f, 0.f);

#pragma unroll 4
    for (int k4 = 0; k4 < DENSE; k4 += 4) {
        u64t w01[4], w23[4];
#pragma unroll
        for (int jj = 0; jj < 4; jj++) {
            float4 wv = *(const float4*)(sWT + (tx + 16 * jj) * SA2 + k4);
            w01[jj] = pk2(wv.x, wv.y); w23[jj] = pk2(wv.z, wv.w);
        }
#pragma unroll
        for (int i = 0; i < 8; i++) {
            float4 av = *(const float4*)(aB + i * SA2 + k4);
            u64t a01 = pk2(av.x, av.y), a23 = pk2(av.z, av.w);
#pragma unroll
            for (int jj = 0; jj < 4; jj++) {
                fma2(acc[i][jj], a01, w01[jj]);
                fma2(acc[i][jj], a23, w23[jj]);
            }
        }
    }

    float cs[4] = {0.f, 0.f, 0.f, 0.f}, cq[4] = {0.f, 0.f, 0.f, 0.f};
#pragma unroll
    for (int i = 0; i < 8; i++) {
        int gr = row0 + ty * 8 + i;
#pragma unroll
        for (int jj = 0; jj < 4; jj++) {
            float2 p = up2(acc[i][jj]);
            float v = p.x + p.y;
            if (gr < N_NODES) Xout[(size_t)gr * HID + tx + 16 * jj] = v;
            cs[jj] += v; cq[jj] += v * v;
        }
    }
#pragma unroll
    for (int jj = 0; jj < 4; jj++) {
        atomicAdd(&sS[tx + 16 * jj], cs[jj]);
        atomicAdd(&sS[HID + tx + 16 * jj], cq[jj]);
    }
    __syncthreads();
    if (t < 128) atomicAdd(&statsOut[t], sS[t]);
}

// ---------------- global mean pool per graph ------------------------------
__global__ void k_pool(const float* __restrict__ X, const int* __restrict__ batch,
                       const float* __restrict__ statsIn,
                       const float* __restrict__ gam, const float* __restrict__ bet) {
    __shared__ float sa[HID], sb[HID];
    __shared__ float sred[4][HID];
    __shared__ int s_lo, s_hi;
    int tid = threadIdx.x, g = blockIdx.x;
    if (tid < HID) {
        float s = statsIn[tid], q = statsIn[HID + tid];
        float m = s * INVN;
        float var = q * INVN - m * m;
        float a = gam[tid] * rsqrtf(var + 1e-5f);
        sa[tid] = a;
        sb[tid] = fmaf(-m, a, bet[tid]);
    }
    if (tid == 0) {
        int lo = 0, hi = N_NODES;
        while (lo < hi) { int mid = (lo + hi) >> 1; if (batch[mid] < g) lo = mid + 1; else hi = mid; }
        s_lo = lo;
        lo = 0; hi = N_NODES; int gg = g + 1;
        while (lo < hi) { int mid = (lo + hi) >> 1; if (batch[mid] < gg) lo = mid + 1; else hi = mid; }
        s_hi = lo;
    }
    __syncthreads();
    int c = tid & 63, rg = tid >> 6;
    float acc = 0.f;
    for (int r = s_lo + rg; r < s_hi; r += 4) {
        float v = fmaf(sa[c], X[(size_t)r * HID + c], sb[c]);
        acc += fmaxf(v, 0.f);
    }
    sred[rg][c] = acc; __syncthreads();
    if (tid < HID) {
        float s = sred[0][c] + sred[1][c] + sred[2][c] + sred[3][c];
        int cnt = s_hi - s_lo;
        g_reps[g * HID + c] = s / (float)(cnt > 0 ? cnt : 1);
    }
}

// ---------------- head BN finalize + tiny GEMMs ---------------------------
__global__ void k_fin(float* __restrict__ stats, const float* __restrict__ g,
                      const float* __restrict__ b, float* __restrict__ tf,
                      int width, float invN) {
    int t = threadIdx.x;
    if (t < width) {
        float s = stats[t], q = stats[width + t];
        float m = s * invN;
        float var = q * invN - m * m;
        float rstd = rsqrtf(var + 1e-5f);
        float a = g[t] * rstd;
        tf[t] = a;
        tf[width + t] = b[t] - m * a;
        stats[t] = 0.f; stats[width + t] = 0.f;
    }
}

__global__ void kf_gemm(const float* __restrict__ A, const float* __restrict__ W,
                        float* __restrict__ out, float* __restrict__ stats,
                        const float* __restrict__ tf, int K, int N) {
    int r = blockIdx.x, n = threadIdx.x;
    float acc = 0.f;
    for (int k = 0; k < K; k++) {
        float av = A[r * K + k];
        if (tf) av = fmaxf(fmaf(tf[k], av, tf[K + k]), 0.f);
        acc = fmaf(av, W[k * N + n], acc);
    }
    out[r * N + n] = acc;
    atomicAdd(&stats[n], acc);
    atomicAdd(&stats[N + n], acc * acc);
}

__global__ void kf_out(const float* __restrict__ T2v, const float* __restrict__ Wlin,
                       const float* __restrict__ blin, float* __restrict__ out) {
    int r = blockIdx.x, o = threadIdx.x;
    if (o < OUTD) {
        float acc = blin[o];
        for (int k = 0; k < DENSE; k++) {
            float av = fmaxf(fmaf(g_tfF[k], T2v[r * DENSE + k], g_tfF[DENSE + k]), 0.f);
            acc = fmaf(av, Wlin[k * OUTD + o], acc);
        }
        out[r * OUTD + o] = acc;
    }
}

// ---------------- launcher ------------------------------------------------
extern "C" void kernel_launch(void* const* d_in, const int* in_sizes, int n_in,
                              void* d_out, int out_size) {
    (void)in_sizes; (void)n_in; (void)out_size;
    const int*   x_idx = (const int*)d_in[0];
    const int*   ei    = (const int*)d_in[1];
    const int*   batch = (const int*)d_in[2];
    const float* emb   = (const float*)d_in[3];
    const float* eps   = (const float*)d_in[4];
    const float* W1    = (const float*)d_in[5];
    const float* g1    = (const float*)d_in[6];
    const float* b1    = (const float*)d_in[7];
    const float* W2    = (const float*)d_in[8];
    const float* g2    = (const float*)d_in[9];
    const float* b2    = (const float*)d_in[10];
    const float* Wf1   = (const float*)d_in[11];
    const float* gf1   = (const float*)d_in[12];
    const float* bf1   = (const float*)d_in[13];
    const float* Wf2   = (const float*)d_in[14];
    const float* gf2   = (const float*)d_in[15];
    const float* bf2   = (const float*)d_in[16];
    const float* Wlin  = (const float*)d_in[17];
    const float* blin  = (const float*)d_in[18];
    float* out = (float*)d_out;

    float *Xa, *Xb, *Y1, *s128, *s64, *sF, *reps, *T1, *T2, *tfF;
    cudaGetSymbolAddress((void**)&Xa,   g_Xa);
    cudaGetSymbolAddress((void**)&Xb,   g_Xb);
    cudaGetSymbolAddress((void**)&Y1,   g_Y1);
    cudaGetSymbolAddress((void**)&s128, g_stats128);
    cudaGetSymbolAddress((void**)&s64,  g_stats64);
    cudaGetSymbolAddress((void**)&sF,   g_statsF);
    cudaGetSymbolAddress((void**)&reps, g_reps);
    cudaGetSymbolAddress((void**)&T1,   g_T1);
    cudaGetSymbolAddress((void**)&T2,   g_T2);
    cudaGetSymbolAddress((void**)&tfF,  g_tfF);

    static const size_t G1_BYTES = G1_SMEM_FLOATS * sizeof(float);
    static const size_t G2_BYTES = G2_SMEM_FLOATS * sizeof(float);
    cudaFuncSetAttribute(k_gemm1f, cudaFuncAttributeMaxDynamicSharedMemorySize, (int)G1_BYTES);
    cudaFuncSetAttribute(k_gemm2,  cudaFuncAttributeMaxDynamicSharedMemorySize, (int)G2_BYTES);

    k_setup<<<(N_NODES + 255) / 256, 256>>>();
    k_hist <<<(N_EDGES + 255) / 256, 256>>>(ei);
    k_scan1<<<SCAN_NB, 256>>>();
    k_scan2<<<1, 128>>>(SCAN_NB);
    k_scan3<<<SCAN_NB, 256>>>();
    k_fill <<<(N_EDGES + 255) / 256, 256>>>(ei);

    const int GEMM_GRID = (N_NODES + 127) / 128;   // 782
    float* Xcur = Xa; float* Xnext = Xb;
    for (int l = 0; l < 4; l++) {
        const float* sIn = (l > 0) ? (s64 + (l - 1) * 2 * HID) : (const float*)0;
        const float* gIn = (l > 0) ? (g2 + (l - 1) * HID) : (const float*)0;
        const float* bIn = (l > 0) ? (b2 + (l - 1) * HID) : (const float*)0;
        k_gemm1f<<<GEMM_GRID, 512, G1_BYTES>>>(x_idx, emb, Xcur, eps,
                                               W1 + (size_t)l * HID * DENSE, Y1,
                                               sIn, gIn, bIn,
                                               s128 + l * 2 * DENSE, l);
        k_gemm2<<<GEMM_GRID, 256, G2_BYTES>>>(Y1, W2 + (size_t)l * DENSE * HID, Xnext,
                                              s128 + l * 2 * DENSE,
                                              g1 + l * DENSE, b1 + l * DENSE,
                                              s64 + l * 2 * HID);
        float* t = Xcur; Xcur = Xnext; Xnext = t;
    }
    k_pool<<<N_GRAPHS, 256>>>(Xcur, batch, s64 + 3 * 2 * HID, g2 + 3 * HID, b2 + 3 * HID);

    const float invG = 1.f / (float)N_GRAPHS;
    kf_gemm<<<N_GRAPHS, DENSE>>>(reps, Wf1, T1, sF, (const float*)0, HID, DENSE);
    k_fin<<<1, DENSE>>>(sF, gf1, bf1, tfF, DENSE, invG);
    kf_gemm<<<N_GRAPHS, DENSE>>>(T1, Wf2, T2, sF, tfF, DENSE, DENSE);
    k_fin<<<1, DENSE>>>(sF, gf2, bf2, tfF, DENSE, invG);
    kf_out<<<N_GRAPHS, 32>>>(T2, Wlin, blin, out);
}

// round 5
// speedup vs baseline: 1.1608x; 1.1608x over previous
#include <cuda_runtime.h>

#define N_NODES 100000
#define N_EDGES 1600000
#define HID 64
#define DENSE 128
#define OUTD 10
#define N_GRAPHS 128
#define SCAN_NB 98   // ceil(100000/1024)
#define INVN (1.f / (float)N_NODES)

typedef unsigned long long u64t;

// ---------------- packed f32x2 helpers ------------------------------------
__device__ __forceinline__ u64t pk2(float lo, float hi) {
    u64t r;
    asm("mov.b64 %0,{%1,%2};" : "=l"(r) : "f"(lo), "f"(hi));
    return r;
}
__device__ __forceinline__ void fma2(u64t& d, u64t a, u64t b) {
    asm("fma.rn.f32x2 %0,%1,%2,%0;" : "+l"(d) : "l"(a), "l"(b));
}
__device__ __forceinline__ float2 up2(u64t v) {
    float2 r;
    asm("mov.b64 {%0,%1},%2;" : "=f"(r.x), "=f"(r.y) : "l"(v));
    return r;
}

// ---------------- device scratch ------------------------------------------
__device__ __align__(16) float g_Xa[N_NODES * HID];
__device__ __align__(16) float g_Xb[N_NODES * HID];
__device__ __align__(16) float g_H [N_NODES * HID];
__device__ __align__(16) float g_Y1[N_NODES * DENSE];
__device__ int   g_deg[N_NODES];
__device__ int   g_rowptr[N_NODES];
__device__ int   g_cursor[N_NODES];
__device__ int   g_col[N_EDGES];
__device__ int   g_bsum[128];
__device__ __align__(16) float g_stats128[4 * 2 * DENSE];  // per-layer
__device__ __align__(16) float g_stats64 [4 * 2 * HID];    // per-layer
__device__ __align__(16) float g_statsF[2 * DENSE];
__device__ __align__(16) float g_tfF[2 * DENSE];
__device__ __align__(16) float g_reps[N_GRAPHS * HID];
__device__ __align__(16) float g_T1[N_GRAPHS * DENSE];
__device__ __align__(16) float g_T2[N_GRAPHS * DENSE];

// ---------------- setup ---------------------------------------------------
__global__ void k_setup() {
    int t = blockIdx.x * blockDim.x + threadIdx.x;
    if (t < N_NODES)          g_deg[t] = 0;
    if (t < 4 * 2 * DENSE)    g_stats128[t] = 0.f;
    if (t < 4 * 2 * HID)      g_stats64[t]  = 0.f;
    if (t < 2 * DENSE)        g_statsF[t] = 0.f;
}

// ---------------- CSR build (keyed by dst, values = src) ------------------
__global__ void k_hist(const int* __restrict__ ei) {
    int e = blockIdx.x * blockDim.x + threadIdx.x;
    if (e < N_EDGES) atomicAdd(&g_deg[ei[N_EDGES + e]], 1);
}

__global__ void k_scan1() {
    __shared__ int ss[256];
    int tid = threadIdx.x;
    int base = blockIdx.x * 1024 + tid * 4;
    int s = 0;
#pragma unroll
    for (int i = 0; i < 4; i++) {
        int idx = base + i;
        if (idx < N_NODES) s += g_deg[idx];
    }
    ss[tid] = s; __syncthreads();
    for (int off = 128; off > 0; off >>= 1) {
        if (tid < off) ss[tid] += ss[tid + off];
        __syncthreads();
    }
    if (tid == 0) g_bsum[blockIdx.x] = ss[0];
}

__global__ void k_scan2(int nblk) {
    __shared__ int ws[4];
    int t = threadIdx.x, lane = t & 31, w = t >> 5;
    int orig = (t < nblk) ? g_bsum[t] : 0;
    int v = orig;
#pragma unroll
    for (int o = 1; o < 32; o <<= 1) {
        int n = __shfl_up_sync(0xFFFFFFFFu, v, o);
        if (lane >= o) v += n;
    }
    if (lane == 31) ws[w] = v;
    __syncthreads();
    int add = 0;
    for (int i = 0; i < w; i++) add += ws[i];
    v += add;
    if (t < nblk) g_bsum[t] = v - orig;
}

__global__ void k_scan3() {
    __shared__ int sc[256];
    int tid = threadIdx.x;
    int base = blockIdx.x * 1024 + tid * 4;
    int d[4]; int s = 0;
#pragma unroll
    for (int i = 0; i < 4; i++) {
        d[i] = (base + i < N_NODES) ? g_deg[base + i] : 0;
        s += d[i];
    }
    sc[tid] = s; __syncthreads();
    for (int off = 1; off < 256; off <<= 1) {
        int v = (tid >= off) ? sc[tid - off] : 0;
        __syncthreads();
        sc[tid] += v;
        __syncthreads();
    }
    int off = g_bsum[blockIdx.x] + sc[tid] - s;
#pragma unroll
    for (int i = 0; i < 4; i++) {
        if (base + i < N_NODES) { g_rowptr[base + i] = off; g_cursor[base + i] = off; off += d[i]; }
    }
}

__global__ void k_fill(const int* __restrict__ ei) {
    int e = blockIdx.x * blockDim.x + threadIdx.x;
    if (e < N_EDGES) {
        int d = ei[N_EDGES + e];
        int p = atomicAdd(&g_cursor[d], 1);
        g_col[p] = ei[e];
    }
}

// ---------------- layer-0 aggregation fused with embedding ---------------
__global__ void __launch_bounds__(256) k_aggr0(const int* __restrict__ x_idx,
                                               const float* __restrict__ emb,
                                               const float* __restrict__ epsArr,
                                               float* __restrict__ Hout) {
    int warp = (blockIdx.x * blockDim.x + threadIdx.x) >> 5;
    if (warp >= N_NODES) return;
    int lane = threadIdx.x & 31, c0 = lane * 2;
    float ev = 1.f + epsArr[0];
    int self = __ldg(&x_idx[warp]);
    float2 xv = *(const float2*)(emb + (size_t)self * HID + c0);
    float s0 = ev * xv.x, s1 = ev * xv.y;
    int start = g_rowptr[warp], deg = g_deg[warp];
    int j = 0;
    for (; j + 1 < deg; j += 2) {
        int n0 = __ldg(&x_idx[g_col[start + j]]);
        int n1 = __ldg(&x_idx[g_col[start + j + 1]]);
        float2 p = *(const float2*)(emb + (size_t)n0 * HID + c0);
        float2 q = *(const float2*)(emb + (size_t)n1 * HID + c0);
        s0 += p.x + q.x; s1 += p.y + q.y;
    }
    if (j < deg) {
        int n0 = __ldg(&x_idx[g_col[start + j]]);
        float2 p = *(const float2*)(emb + (size_t)n0 * HID + c0);
        s0 += p.x; s1 += p.y;
    }
    *(float2*)(Hout + (size_t)warp * HID + c0) = make_float2(s0, s1);
}

// ---------------- aggregation l>=1: f = relu(BN affine) ------------------
__global__ void __launch_bounds__(256) k_aggr(const float* __restrict__ X,
                                              float* __restrict__ Hout,
                                              const float* __restrict__ epsArr,
                                              const float* __restrict__ statsIn,
                                              const float* __restrict__ gam,
                                              const float* __restrict__ bet,
                                              int layer) {
    __shared__ float sa[HID], sb[HID];
    int tid = threadIdx.x;
    if (tid < HID) {
        float s = statsIn[tid], q = statsIn[HID + tid];
        float m = s * INVN;
        float var = q * INVN - m * m;
        float a = gam[tid] * rsqrtf(var + 1e-5f);
        sa[tid] = a;
        sb[tid] = fmaf(-m, a, bet[tid]);
    }
    __syncthreads();
    int warp = (blockIdx.x * blockDim.x + tid) >> 5;
    if (warp >= N_NODES) return;
    int lane = tid & 31, c0 = lane * 2;
    float a0 = sa[c0], a1 = sa[c0 + 1], b0 = sb[c0], b1 = sb[c0 + 1];
    float ev = 1.f + epsArr[layer];

    float2 xv = *(const float2*)(X + (size_t)warp * HID + c0);
    float s0 = ev * fmaxf(fmaf(a0, xv.x, b0), 0.f);
    float s1 = ev * fmaxf(fmaf(a1, xv.y, b1), 0.f);

    int start = g_rowptr[warp], deg = g_deg[warp];
    int j = 0;
    for (; j + 1 < deg; j += 2) {
        int n0 = g_col[start + j], n1 = g_col[start + j + 1];
        float2 p = *(const float2*)(X + (size_t)n0 * HID + c0);
        float2 q = *(const float2*)(X + (size_t)n1 * HID + c0);
        s0 += fmaxf(fmaf(a0, p.x, b0), 0.f) + fmaxf(fmaf(a0, q.x, b0), 0.f);
        s1 += fmaxf(fmaf(a1, p.y, b1), 0.f) + fmaxf(fmaf(a1, q.y, b1), 0.f);
    }
    if (j < deg) {
        int n0 = g_col[start + j];
        float2 p = *(const float2*)(X + (size_t)n0 * HID + c0);
        s0 += fmaxf(fmaf(a0, p.x, b0), 0.f);
        s1 += fmaxf(fmaf(a1, p.y, b1), 0.f);
    }
    *(float2*)(Hout + (size_t)warp * HID + c0) = make_float2(s0, s1);
}

// ============ GEMM1: Y1 = H @ W1 (k-paired FFMA2, 512 thr) ================
#define SA1 68                       // 64 + 4 pad
#define G1_SMEM_FLOATS (128*SA1 + 128*SA1 + 2*DENSE)
__global__ void __launch_bounds__(512, 1) k_gemm1(const float* __restrict__ A,
                                                  const float* __restrict__ W,
                                                  float* __restrict__ Y,
                                                  float* __restrict__ statsOut) {
    extern __shared__ float sm[];
    float* sA  = sm;                     // [128][SA1]
    float* sWT = sm + 128 * SA1;         // [128 cols][SA1]
    float* sS  = sWT + 128 * SA1;        // [256]
    int t = threadIdx.x;
    int row0 = blockIdx.x * 128;

    if (t < 256) sS[t] = 0.f;
    // W transpose: W[k][c] -> sWT[c][k]
    for (int idx = t; idx < HID * DENSE; idx += 512) {
        int k = idx >> 7, c = idx & 127;
        sWT[c * SA1 + k] = W[idx];
    }
    {   // A tile: 4 threads per row, 16 floats each
        int row = t >> 2, th = t & 3, c0 = th * 16;
        int gr = row0 + row;
        float4* dst = (float4*)(sA + row * SA1 + c0);
        if (gr < N_NODES) {
            const float4* src = (const float4*)(A + (size_t)gr * HID + c0);
#pragma unroll
            for (int i = 0; i < 4; i++) dst[i] = src[i];
        } else {
#pragma unroll
            for (int i = 0; i < 4; i++) dst[i] = make_float4(0.f, 0.f, 0.f, 0.f);
        }
    }
    __syncthreads();

    // ---- mainloop: 8 rows x 4 cols per thread, k-paired FFMA2 ----
    int tx = t & 31, ty = t >> 5;
    const float* aB = sA + ty * 8 * SA1;
    u64t acc[8][4];
#pragma unroll
    for (int i = 0; i < 8; i++)
#pragma unroll
        for (int j = 0; j < 4; j++) acc[i][j] = pk2(0.f, 0.f);

#pragma unroll 4
    for (int k4 = 0; k4 < HID; k4 += 4) {
        u64t w01[4], w23[4];
#pragma unroll
        for (int jj = 0; jj < 4; jj++) {
            float4 wv = *(const float4*)(sWT + (tx + 32 * jj) * SA1 + k4);
            w01[jj] = pk2(wv.x, wv.y); w23[jj] = pk2(wv.z, wv.w);
        }
#pragma unroll
        for (int i = 0; i < 8; i++) {
            float4 av = *(const float4*)(aB + i * SA1 + k4);
            u64t a01 = pk2(av.x, av.y), a23 = pk2(av.z, av.w);
#pragma unroll
            for (int jj = 0; jj < 4; jj++) {
                fma2(acc[i][jj], a01, w01[jj]);
                fma2(acc[i][jj], a23, w23[jj]);
            }
        }
    }

    float cs[4] = {0.f, 0.f, 0.f, 0.f}, cq[4] = {0.f, 0.f, 0.f, 0.f};
#pragma unroll
    for (int i = 0; i < 8; i++) {
        int gr = row0 + ty * 8 + i;
#pragma unroll
        for (int jj = 0; jj < 4; jj++) {
            float2 p = up2(acc[i][jj]);
            float v = p.x + p.y;
            if (gr < N_NODES) Y[(size_t)gr * DENSE + tx + 32 * jj] = v;
            cs[jj] += v; cq[jj] += v * v;
        }
    }
#pragma unroll
    for (int jj = 0; jj < 4; jj++) {
        atomicAdd(&sS[tx + 32 * jj], cs[jj]);
        atomicAdd(&sS[DENSE + tx + 32 * jj], cq[jj]);
    }
    __syncthreads();
    if (t < 256) atomicAdd(&statsOut[t], sS[t]);
}

// ============ GEMM2: X' = relu(BN(Y1)) @ W2 (k-paired FFMA2) ==============
#define SA2 132                      // 128 + 4 pad
#define G2_SMEM_FLOATS (128*SA2 + 64*SA2 + 3*DENSE)
__global__ void __launch_bounds__(256, 2) k_gemm2(const float* __restrict__ Yin,
                                                  const float* __restrict__ W,
                                                  float* __restrict__ Xout,
                                                  const float* __restrict__ statsIn,
                                                  const float* __restrict__ gam,
                                                  const float* __restrict__ bet,
                                                  float* __restrict__ statsOut) {
    extern __shared__ float sm[];
    float* sA  = sm;                   // [128][SA2]
    float* sWT = sm + 128 * SA2;       // [64 cols][SA2]
    float* sTa = sWT + 64 * SA2;       // [128]
    float* sTb = sTa + DENSE;          // [128]
    float* sS  = sTb + DENSE;          // [128]
    int t = threadIdx.x;
    int row0 = blockIdx.x * 128;

    if (t < DENSE) {
        float s = statsIn[t], q = statsIn[DENSE + t];
        float m = s * INVN;
        float var = q * INVN - m * m;
        float a = gam[t] * rsqrtf(var + 1e-5f);
        sTa[t] = a;
        sTb[t] = fmaf(-m, a, bet[t]);
    }
    if (t < 128) sS[t] = 0.f;
    __syncthreads();

    // W transpose: W[k][c] (128x64) -> sWT[c][k]
    for (int idx = t; idx < DENSE * HID; idx += 256) {
        int k = idx >> 6, c = idx & 63;
        sWT[c * SA2 + k] = W[idx];
    }
    {   // A tile with BN+relu transform
        int r = t >> 1, kh = (t & 1) * 64;
        int gr = row0 + r;
        float4* dst = (float4*)(sA + r * SA2 + kh);
        if (gr < N_NODES) {
            const float4* src = (const float4*)(Yin + (size_t)gr * DENSE + kh);
#pragma unroll
            for (int i = 0; i < 16; i++) {
                float4 y = src[i];
                float4 ta = *(const float4*)(sTa + kh + i * 4);
                float4 tb = *(const float4*)(sTb + kh + i * 4);
                float4 v;
                v.x = fmaxf(fmaf(ta.x, y.x, tb.x), 0.f);
                v.y = fmaxf(fmaf(ta.y, y.y, tb.y), 0.f);
                v.z = fmaxf(fmaf(ta.z, y.z, tb.z), 0.f);
                v.w = fmaxf(fmaf(ta.w, y.w, tb.w), 0.f);
                dst[i] = v;
            }
        } else {
#pragma unroll
            for (int i = 0; i < 16; i++) dst[i] = make_float4(0.f, 0.f, 0.f, 0.f);
        }
    }
    __syncthreads();

    int tx = t & 15, ty = t >> 4;
    const float* aB = sA + ty * 8 * SA2;
    u64t acc[8][4];
#pragma unroll
    for (int i = 0; i < 8; i++)
#pragma unroll
        for (int j = 0; j < 4; j++) acc[i][j] = pk2(0.f, 0.f);

#pragma unroll 4
    for (int k4 = 0; k4 < DENSE; k4 += 4) {
        u64t w01[4], w23[4];
#pragma unroll
        for (int jj = 0; jj < 4; jj++) {
            float4 wv = *(const float4*)(sWT + (tx + 16 * jj) * SA2 + k4);
            w01[jj] = pk2(wv.x, wv.y); w23[jj] = pk2(wv.z, wv.w);
        }
#pragma unroll
        for (int i = 0; i < 8; i++) {
            float4 av = *(const float4*)(aB + i * SA2 + k4);
            u64t a01 = pk2(av.x, av.y), a23 = pk2(av.z, av.w);
#pragma unroll
            for (int jj = 0; jj < 4; jj++) {
                fma2(acc[i][jj], a01, w01[jj]);
                fma2(acc[i][jj], a23, w23[jj]);
            }
        }
    }

    float cs[4] = {0.f, 0.f, 0.f, 0.f}, cq[4] = {0.f, 0.f, 0.f, 0.f};
#pragma unroll
    for (int i = 0; i < 8; i++) {
        int gr = row0 + ty * 8 + i;
#pragma unroll
        for (int jj = 0; jj < 4; jj++) {
            float2 p = up2(acc[i][jj]);
            float v = p.x + p.y;
            if (gr < N_NODES) Xout[(size_t)gr * HID + tx + 16 * jj] = v;
            cs[jj] += v; cq[jj] += v * v;
        }
    }
#pragma unroll
    for (int jj = 0; jj < 4; jj++) {
        atomicAdd(&sS[tx + 16 * jj], cs[jj]);
        atomicAdd(&sS[HID + tx + 16 * jj], cq[jj]);
    }
    __syncthreads();
    if (t < 128) atomicAdd(&statsOut[t], sS[t]);
}

// ---------------- global mean pool per graph ------------------------------
__global__ void k_pool(const float* __restrict__ X, const int* __restrict__ batch,
                       const float* __restrict__ statsIn,
                       const float* __restrict__ gam, const float* __restrict__ bet) {
    __shared__ float sa[HID], sb[HID];
    __shared__ float sred[4][HID];
    __shared__ int s_lo, s_hi;
    int tid = threadIdx.x, g = blockIdx.x;
    if (tid < HID) {
        float s = statsIn[tid], q = statsIn[HID + tid];
        float m = s * INVN;
        float var = q * INVN - m * m;
        float a = gam[tid] * rsqrtf(var + 1e-5f);
        sa[tid] = a;
        sb[tid] = fmaf(-m, a, bet[tid]);
    }
    if (tid == 0) {
        int lo = 0, hi = N_NODES;
        while (lo < hi) { int mid = (lo + hi) >> 1; if (batch[mid] < g) lo = mid + 1; else hi = mid; }
        s_lo = lo;
        lo = 0; hi = N_NODES; int gg = g + 1;
        while (lo < hi) { int mid = (lo + hi) >> 1; if (batch[mid] < gg) lo = mid + 1; else hi = mid; }
        s_hi = lo;
    }
    __syncthreads();
    int c = tid & 63, rg = tid >> 6;
    float acc = 0.f;
    for (int r = s_lo + rg; r < s_hi; r += 4) {
        float v = fmaf(sa[c], X[(size_t)r * HID + c], sb[c]);
        acc += fmaxf(v, 0.f);
    }
    sred[rg][c] = acc; __syncthreads();
    if (tid < HID) {
        float s = sred[0][c] + sred[1][c] + sred[2][c] + sred[3][c];
        int cnt = s_hi - s_lo;
        g_reps[g * HID + c] = s / (float)(cnt > 0 ? cnt : 1);
    }
}

// ---------------- head BN finalize + tiny GEMMs ---------------------------
__global__ void k_fin(float* __restrict__ stats, const float* __restrict__ g,
                      const float* __restrict__ b, float* __restrict__ tf,
                      int width, float invN) {
    int t = threadIdx.x;
    if (t < width) {
        float s = stats[t], q = stats[width + t];
        float m = s * invN;
        float var = q * invN - m * m;
        float rstd = rsqrtf(var + 1e-5f);
        float a = g[t] * rstd;
        tf[t] = a;
        tf[width + t] = b[t] - m * a;
        stats[t] = 0.f; stats[width + t] = 0.f;
    }
}

__global__ void kf_gemm(const float* __restrict__ A, const float* __restrict__ W,
                        float* __restrict__ out, float* __restrict__ stats,
                        const float* __restrict__ tf, int K, int N) {
    int r = blockIdx.x, n = threadIdx.x;
    float acc = 0.f;
    for (int k = 0; k < K; k++) {
        float av = A[r * K + k];
        if (tf) av = fmaxf(fmaf(tf[k], av, tf[K + k]), 0.f);
        acc = fmaf(av, W[k * N + n], acc);
    }
    out[r * N + n] = acc;
    atomicAdd(&stats[n], acc);
    atomicAdd(&stats[N + n], acc * acc);
}

__global__ void kf_out(const float* __restrict__ T2v, const float* __restrict__ Wlin,
                       const float* __restrict__ blin, float* __restrict__ out) {
    int r = blockIdx.x, o = threadIdx.x;
    if (o < OUTD) {
        float acc = blin[o];
        for (int k = 0; k < DENSE; k++) {
            float av = fmaxf(fmaf(g_tfF[k], T2v[r * DENSE + k], g_tfF[DENSE + k]), 0.f);
            acc = fmaf(av, Wlin[k * OUTD + o], acc);
        }
        out[r * OUTD + o] = acc;
    }
}

// ---------------- launcher ------------------------------------------------
extern "C" void kernel_launch(void* const* d_in, const int* in_sizes, int n_in,
                              void* d_out, int out_size) {
    (void)in_sizes; (void)n_in; (void)out_size;
    const int*   x_idx = (const int*)d_in[0];
    const int*   ei    = (const int*)d_in[1];
    const int*   batch = (const int*)d_in[2];
    const float* emb   = (const float*)d_in[3];
    const float* eps   = (const float*)d_in[4];
    const float* W1    = (const float*)d_in[5];
    const float* g1    = (const float*)d_in[6];
    const float* b1    = (const float*)d_in[7];
    const float* W2    = (const float*)d_in[8];
    const float* g2    = (const float*)d_in[9];
    const float* b2    = (const float*)d_in[10];
    const float* Wf1   = (const float*)d_in[11];
    const float* gf1   = (const float*)d_in[12];
    const float* bf1   = (const float*)d_in[13];
    const float* Wf2   = (const float*)d_in[14];
    const float* gf2   = (const float*)d_in[15];
    const float* bf2   = (const float*)d_in[16];
    const float* Wlin  = (const float*)d_in[17];
    const float* blin  = (const float*)d_in[18];
    float* out = (float*)d_out;

    float *Xa, *Xb, *H, *Y1, *s128, *s64, *sF, *reps, *T1, *T2, *tfF;
    cudaGetSymbolAddress((void**)&Xa,   g_Xa);
    cudaGetSymbolAddress((void**)&Xb,   g_Xb);
    cudaGetSymbolAddress((void**)&H,    g_H);
    cudaGetSymbolAddress((void**)&Y1,   g_Y1);
    cudaGetSymbolAddress((void**)&s128, g_stats128);
    cudaGetSymbolAddress((void**)&s64,  g_stats64);
    cudaGetSymbolAddress((void**)&sF,   g_statsF);
    cudaGetSymbolAddress((void**)&reps, g_reps);
    cudaGetSymbolAddress((void**)&T1,   g_T1);
    cudaGetSymbolAddress((void**)&T2,   g_T2);
    cudaGetSymbolAddress((void**)&tfF,  g_tfF);

    static const size_t G1_BYTES = G1_SMEM_FLOATS * sizeof(float);
    static const size_t G2_BYTES = G2_SMEM_FLOATS * sizeof(float);
    cudaFuncSetAttribute(k_gemm1, cudaFuncAttributeMaxDynamicSharedMemorySize, (int)G1_BYTES);
    cudaFuncSetAttribute(k_gemm2, cudaFuncAttributeMaxDynamicSharedMemorySize, (int)G2_BYTES);

    k_setup<<<(N_NODES + 255) / 256, 256>>>();
    k_hist <<<(N_EDGES + 255) / 256, 256>>>(ei);
    k_scan1<<<SCAN_NB, 256>>>();
    k_scan2<<<1, 128>>>(SCAN_NB);
    k_scan3<<<SCAN_NB, 256>>>();
    k_fill <<<(N_EDGES + 255) / 256, 256>>>(ei);

    const int GEMM_GRID = (N_NODES + 127) / 128;   // 782
    float* Xcur = Xa; float* Xnext = Xb;
    for (int l = 0; l < 4; l++) {
        if (l == 0)
            k_aggr0<<<(N_NODES * 32 + 255) / 256, 256>>>(x_idx, emb, eps, H);
        else
            k_aggr<<<(N_NODES * 32 + 255) / 256, 256>>>(
                Xcur, H, eps, s64 + (l - 1) * 2 * HID,
                g2 + (l - 1) * HID, b2 + (l - 1) * HID, l);
        k_gemm1<<<GEMM_GRID, 512, G1_BYTES>>>(H, W1 + (size_t)l * HID * DENSE, Y1,
                                              s128 + l * 2 * DENSE);
        k_gemm2<<<GEMM_GRID, 256, G2_BYTES>>>(Y1, W2 + (size_t)l * DENSE * HID, Xnext,
                                              s128 + l * 2 * DENSE,
                                              g1 + l * DENSE, b1 + l * DENSE,
                                              s64 + l * 2 * HID);
        float* t = Xcur; Xcur = Xnext; Xnext = t;
    }
    k_pool<<<N_GRAPHS, 256>>>(Xcur, batch, s64 + 3 * 2 * HID, g2 + 3 * HID, b2 + 3 * HID);

    const float invG = 1.f / (float)N_GRAPHS;
    kf_gemm<<<N_GRAPHS, DENSE>>>(reps, Wf1, T1, sF, (const float*)0, HID, DENSE);
    k_fin<<<1, DENSE>>>(sF, gf1, bf1, tfF, DENSE, invG);
    kf_gemm<<<N_GRAPHS, DENSE>>>(T1, Wf2, T2, sF, tfF, DENSE, DENSE);
    k_fin<<<1, DENSE>>>(sF, gf2, bf2, tfF, DENSE, invG);
    kf_out<<<N_GRAPHS, 32>>>(T2, Wlin, blin, out);
}